// round 4
// baseline (speedup 1.0000x reference)
#include <cuda_runtime.h>
#include <cstdint>

// ---- Problem constants (must match reference exactly) ----
#define GX 432
#define GY 496
#define VTOTAL (GX * GY)            // 214272 (GZ == 1)
#define MAX_VOX 160000
#define NPTS 200000                  // points per batch
#define P_TOTAL 800000               // 4 batches
#define THREADS 1024
#define NBLK 148                     // == B300 SM count; <= GB300's 152 -> all blocks resident
#define NT (THREADS * NBLK)
#define CHUNK 1024
#define NCHUNK ((VTOTAL + CHUNK - 1) / CHUNK)   // 210

// ---- Scratch (device globals: no allocations allowed) ----
__device__ float4   g_sums[VTOTAL];     // zero-init at load; reset in-kernel each run
__device__ int      g_counts[VTOTAL];   // "
__device__ unsigned g_agg[NCHUNK];      // chunk occupancy aggregates (+1 encoded; 0 = not ready)
__device__ unsigned g_ctr;              // monotonic grid-barrier counter (never reset)

__global__ void __launch_bounds__(THREADS)
k_fused(const float* __restrict__ in, float4* __restrict__ out4) {
    const int tid  = threadIdx.x;
    const int b    = blockIdx.x;
    const int lane = tid & 31;
    const int wid  = tid >> 5;

    __shared__ int ws[32];
    __shared__ int s_bcast;

    // ---------- phase 0: reset this block's aggregate slots (pre-barrier) ----------
    if (tid < 2) {
        int c = b + tid * NBLK;
        if (c < NCHUNK) *(volatile unsigned*)&g_agg[c] = 0u;
    }

    // ---------- phase 1: scatter-accumulate points ----------
    // clouds layout (B, C, N): x = in[b*4N + n], y = +N, z = +2N, w = +3N
    for (int p = b * THREADS + tid; p < P_TOTAL; p += NT) {
        int bb = p / NPTS;
        int n  = p - bb * NPTS;
        const float* base = in + (size_t)bb * (4 * NPTS);
        float x = base[n];
        float y = base[NPTS + n];
        float z = base[2 * NPTS + n];
        float w = base[3 * NPTS + n];

        // IEEE-exact, matching JAX f32: floor((coord - low) / vsz)
        // low.x = 0 -> sub is identity; z: /4.0 == *0.25 bit-exact
        float fx = floorf(__fdiv_rn(x, 0.16f));
        float fy = floorf(__fdiv_rn(__fsub_rn(y, -39.68f), 0.16f));
        float fz = floorf(__fmul_rn(__fsub_rn(z, -3.0f), 0.25f));
        int cx = (int)fx, cy = (int)fy, cz = (int)fz;

        if (cx >= 0 && cx < GX && cy >= 0 && cy < GY && cz == 0) {
            int lin = cy * GX + cx;
            atomicAdd(&g_sums[lin], make_float4(x, y, z, w));  // 128-bit RED (sm_90+)
            atomicAdd(&g_counts[lin], 1);
        }
    }

    // ---------- grid barrier (monotonic counter; all 148 blocks resident) ----------
    __threadfence();
    __syncthreads();
    if (tid == 0) {
        unsigned my = atomicAdd(&g_ctr, 1u) + 1u;
        unsigned target = ((my + NBLK - 1u) / NBLK) * NBLK;   // = NBLK * (run+1)
        while (*(volatile unsigned*)&g_ctr < target) { }
    }
    __syncthreads();

    // ---------- phase 2a: publish occupancy aggregate for each owned chunk ----------
    for (int c = b; c < NCHUNK; c += NBLK) {
        int v = c * CHUNK + tid;
        int cnt = (v < VTOTAL) ? __ldcg(&g_counts[v]) : 0;
        unsigned m = __ballot_sync(0xffffffffu, cnt > 0);
        if (lane == 0) ws[wid] = __popc(m);
        __syncthreads();
        if (wid == 0) {
            int s = ws[lane];
            #pragma unroll
            for (int o = 16; o > 0; o >>= 1) s += __shfl_down_sync(0xffffffffu, s, o);
            if (lane == 0) *(volatile unsigned*)&g_agg[c] = (unsigned)s + 1u;
        }
        __syncthreads();
    }

    // ---------- phase 2b: lookback offset + local prefix + write means + reset ----------
    for (int c = b; c < NCHUNK; c += NBLK) {
        // sum of aggregates of all chunks < c (depth-1 lookback: one thread per chunk)
        int val = 0;
        if (tid < c) {
            unsigned a;
            do { a = *(volatile unsigned*)&g_agg[tid]; } while (a == 0u);
            val = (int)a - 1;
        }
        #pragma unroll
        for (int o = 16; o > 0; o >>= 1) val += __shfl_down_sync(0xffffffffu, val, o);
        if (lane == 0) ws[wid] = val;
        __syncthreads();
        if (wid == 0) {
            int s = ws[lane];
            #pragma unroll
            for (int o = 16; o > 0; o >>= 1) s += __shfl_down_sync(0xffffffffu, s, o);
            if (lane == 0) s_bcast = s;
        }
        __syncthreads();
        int prev = s_bcast;

        int v = c * CHUNK + tid;
        int cnt = (v < VTOTAL) ? __ldcg(&g_counts[v]) : 0;
        unsigned m = __ballot_sync(0xffffffffu, cnt > 0);
        __syncthreads();                       // protect ws reuse (s_bcast consumed)
        if (lane == 0) ws[wid] = __popc(m);
        __syncthreads();
        if (wid == 0) {
            int s = ws[lane];
            int incl = s;
            #pragma unroll
            for (int o = 1; o < 32; o <<= 1) {
                int u = __shfl_up_sync(0xffffffffu, incl, o);
                if (lane >= o) incl += u;
            }
            ws[lane] = incl - s;               // exclusive per-warp offsets
        }
        __syncthreads();

        if (cnt > 0) {
            int seg = prev + ws[wid] + __popc(m & ((1u << lane) - 1u));
            if (seg < MAX_VOX) {
                const float4* sp = (const float4*)&g_sums[v];
                float4 s4 = __ldcg(sp);
                float fc = (float)cnt;
                out4[seg] = make_float4(__fdiv_rn(s4.x, fc),
                                        __fdiv_rn(s4.y, fc),
                                        __fdiv_rn(s4.z, fc),
                                        __fdiv_rn(s4.w, fc));
            }
        }

        // in-place reset for next replay (replaces the K0 zeroing kernel)
        if (v < VTOTAL) {
            g_sums[v] = make_float4(0.f, 0.f, 0.f, 0.f);
            g_counts[v] = 0;
        }
        __syncthreads();                       // ws/s_bcast reuse next iteration
    }
}

// ============================================================
extern "C" void kernel_launch(void* const* d_in, const int* in_sizes, int n_in,
                              void* d_out, int out_size) {
    const float* clouds = (const float*)d_in[0];
    float4* out4 = (float4*)d_out;
    k_fused<<<NBLK, THREADS>>>(clouds, out4);
}

// round 15
// speedup vs baseline: 1.0890x; 1.0890x over previous
#include <cuda_runtime.h>
#include <cstdint>

// ---- Problem constants (must match reference exactly) ----
#define GX 432
#define GY 496
#define VTOTAL (GX * GY)            // 214272 (GZ == 1)
#define MAX_VOX 160000
#define NPTS 200000                  // points per batch
#define NBATCH 4
#define CHUNK 1024
#define NCHUNK ((VTOTAL + CHUNK - 1) / CHUNK)   // 210

// ---- Scratch (device globals: no allocations allowed) ----
__device__ float4   g_sums[VTOTAL];     // zero at load; reset in node B each run
__device__ int      g_counts[VTOTAL];   // "
__device__ unsigned g_agg[NCHUNK];      // chunk occupancy (+1 encoded; 0 = not ready)

// ============================================================
// Node A: scatter-accumulate. One point per thread, batch = blockIdx.y.
// Also resets g_agg flags for node B (graph edge orders A before B).
// ============================================================
__global__ void __launch_bounds__(256)
k_accum(const float* __restrict__ in) {
    if (blockIdx.x == 0 && blockIdx.y == 0 && threadIdx.x < NCHUNK) {
        *(volatile unsigned*)&g_agg[threadIdx.x] = 0u;
    }

    int n = blockIdx.x * 256 + threadIdx.x;
    if (n >= NPTS) return;
    const float* base = in + (size_t)blockIdx.y * (4 * NPTS);

    float x = base[n];
    float y = base[NPTS + n];
    float z = base[2 * NPTS + n];
    float w = base[3 * NPTS + n];

    // IEEE-exact, matching JAX f32: floor((coord - low) / vsz)
    // low.x = 0 -> sub identity; z: /4.0 == *0.25 bit-exact
    float fx = floorf(__fdiv_rn(x, 0.16f));
    float fy = floorf(__fdiv_rn(__fsub_rn(y, -39.68f), 0.16f));
    float fz = floorf(__fmul_rn(__fsub_rn(z, -3.0f), 0.25f));
    int cx = (int)fx, cy = (int)fy, cz = (int)fz;

    if (cx >= 0 && cx < GX && cy >= 0 && cy < GY && cz == 0) {
        int lin = cy * GX + cx;
        atomicAdd(&g_sums[lin], make_float4(x, y, z, w));  // 128-bit RED (sm_90+)
        atomicAdd(&g_counts[lin], 1);
    }
}

// ============================================================
// Node B: decoupled-lookback compaction + mean + in-place reset.
// 210 blocks x 1024 threads; block c owns chunk c.
//   1) block-reduce occupancy -> publish g_agg[c] = total+1
//   2) lookback: sum g_agg[0..c-1] (spin until published) -> prev
//   3) local ballot/popc prefix -> seg = prev + local
//   4) write mean; reset g_sums/g_counts (owner-exclusive)
// Publish precedes lookback, so blocks drain in bid order: deadlock-free.
// ============================================================
__global__ void __launch_bounds__(1024, 2)
k_post(float4* __restrict__ out4) {
    const int tid  = threadIdx.x;
    const int c    = blockIdx.x;
    const int lane = tid & 31;
    const int wid  = tid >> 5;

    __shared__ int ws[32];
    __shared__ int s_prev;

    const int v = c * CHUNK + tid;
    const int cnt = (v < VTOTAL) ? __ldcg(&g_counts[v]) : 0;
    const unsigned m = __ballot_sync(0xffffffffu, cnt > 0);

    // ---- 1) block total + publish ----
    if (lane == 0) ws[wid] = __popc(m);
    __syncthreads();
    if (wid == 0) {
        int s = ws[lane];
        #pragma unroll
        for (int o = 16; o > 0; o >>= 1) s += __shfl_down_sync(0xffffffffu, s, o);
        if (lane == 0) *(volatile unsigned*)&g_agg[c] = (unsigned)s + 1u;
    }

    // ---- 2) lookback over prior chunks (one per thread, <= 209) ----
    int val = 0;
    if (tid < c) {
        unsigned a;
        do { a = *(volatile unsigned*)&g_agg[tid]; } while (a == 0u);
        val = (int)a - 1;
    }
    #pragma unroll
    for (int o = 16; o > 0; o >>= 1) val += __shfl_down_sync(0xffffffffu, val, o);
    __syncthreads();                 // ws: totals consumed above, reuse for lookback
    if (lane == 0) ws[wid] = val;
    __syncthreads();
    if (wid == 0) {
        int s = ws[lane];
        #pragma unroll
        for (int o = 16; o > 0; o >>= 1) s += __shfl_down_sync(0xffffffffu, s, o);
        if (lane == 0) s_prev = s;
    }
    __syncthreads();
    const int prev = s_prev;

    // ---- 3) local exclusive prefix of occupancy ----
    __syncthreads();
    if (lane == 0) ws[wid] = __popc(m);
    __syncthreads();
    if (wid == 0) {
        int s = ws[lane];
        int incl = s;
        #pragma unroll
        for (int o = 1; o < 32; o <<= 1) {
            int u = __shfl_up_sync(0xffffffffu, incl, o);
            if (lane >= o) incl += u;
        }
        ws[lane] = incl - s;         // exclusive per-warp offsets
    }
    __syncthreads();

    // ---- 4) write mean + reset ----
    if (cnt > 0) {
        int seg = prev + ws[wid] + __popc(m & ((1u << lane) - 1u));
        if (seg < MAX_VOX) {
            float4 s4 = __ldcg((const float4*)&g_sums[v]);
            float fc = (float)cnt;
            out4[seg] = make_float4(__fdiv_rn(s4.x, fc),
                                    __fdiv_rn(s4.y, fc),
                                    __fdiv_rn(s4.z, fc),
                                    __fdiv_rn(s4.w, fc));
        }
    }
    if (v < VTOTAL) {
        g_sums[v] = make_float4(0.f, 0.f, 0.f, 0.f);
        g_counts[v] = 0;
    }
}

// ============================================================
extern "C" void kernel_launch(void* const* d_in, const int* in_sizes, int n_in,
                              void* d_out, int out_size) {
    const float* clouds = (const float*)d_in[0];
    float4* out4 = (float4*)d_out;

    dim3 agrid((NPTS + 255) / 256, NBATCH);   // 782 x 4 blocks
    k_accum<<<agrid, 256>>>(clouds);
    k_post<<<NCHUNK, CHUNK>>>(out4);
}

// round 16
// speedup vs baseline: 1.0905x; 1.0014x over previous
#include <cuda_runtime.h>
#include <cstdint>

// ---- Problem constants (must match reference exactly) ----
#define GX 432
#define GY 496
#define VTOTAL (GX * GY)            // 214272 (GZ == 1)
#define MAX_VOX 160000
#define NPTS 200000                  // points per batch
#define NBATCH 4
#define NW ((VTOTAL + 31) / 32)     // 6696 warp-masks (exact: 214272/32)
#define PERT 7                       // masks per thread in the scan (1024*7 >= 6696)

// ---- Scratch (device globals: no allocations allowed) ----
__device__ float4   g_sums[VTOTAL];   // zero at load; reset in k_out each run
__device__ int      g_counts[VTOTAL]; // "
__device__ unsigned g_mask[NW];       // 32-voxel occupancy bitmasks (overwritten each run)
__device__ int      g_woff[NW];       // exclusive voxel-rank offset per warp-group

// ============================================================
// K1: scatter-accumulate. One point per thread, batch = blockIdx.y.
// ============================================================
__global__ void __launch_bounds__(256)
k_accum(const float* __restrict__ in) {
    int n = blockIdx.x * 256 + threadIdx.x;
    if (n >= NPTS) return;
    const float* base = in + (size_t)blockIdx.y * (4 * NPTS);

    float x = base[n];
    float y = base[NPTS + n];
    float z = base[2 * NPTS + n];
    float w = base[3 * NPTS + n];

    // IEEE-exact, matching JAX f32: floor((coord - low) / vsz)
    // low.x = 0 -> sub identity; z: /4.0 == *0.25 bit-exact
    float fx = floorf(__fdiv_rn(x, 0.16f));
    float fy = floorf(__fdiv_rn(__fsub_rn(y, -39.68f), 0.16f));
    float fz = floorf(__fmul_rn(__fsub_rn(z, -3.0f), 0.25f));
    int cx = (int)fx, cy = (int)fy, cz = (int)fz;

    if (cx >= 0 && cx < GX && cy >= 0 && cy < GY && cz == 0) {
        int lin = cy * GX + cx;
        atomicAdd(&g_sums[lin], make_float4(x, y, z, w));  // 128-bit RED (sm_90+)
        atomicAdd(&g_counts[lin], 1);
    }
}

// ============================================================
// K2: per-32-voxel occupancy bitmasks. No smem, no syncthreads.
// ============================================================
__global__ void __launch_bounds__(1024)
k_mask() {
    int v = blockIdx.x * 1024 + threadIdx.x;
    int cnt = (v < VTOTAL) ? __ldcg(&g_counts[v]) : 0;
    unsigned m = __ballot_sync(0xffffffffu, cnt > 0);
    int gw = v >> 5;
    if ((v & 31) == 0 && gw < NW) g_mask[gw] = m;
}

// ============================================================
// K3: exclusive scan of the 6696 mask popcounts -> g_woff.
// One block of 1024; thread t owns masks [7t, 7t+7).
// ============================================================
__global__ void __launch_bounds__(1024)
k_scanw() {
    const int t = threadIdx.x;
    const int lane = t & 31;
    const int wid  = t >> 5;
    __shared__ int wtot[32];

    int pre[PERT];
    int run = 0;
    int base_i = t * PERT;
    #pragma unroll
    for (int i = 0; i < PERT; i++) {
        int idx = base_i + i;
        int c = (idx < NW) ? __popc(g_mask[idx]) : 0;
        pre[i] = run;           // exclusive prefix within thread
        run += c;
    }

    // warp-inclusive scan of thread totals
    int incl = run;
    #pragma unroll
    for (int o = 1; o < 32; o <<= 1) {
        int u = __shfl_up_sync(0xffffffffu, incl, o);
        if (lane >= o) incl += u;
    }
    int wexcl = incl - run;     // exclusive within warp
    if (lane == 31) wtot[wid] = incl;
    __syncthreads();
    if (wid == 0) {
        int s = wtot[lane];
        int i2 = s;
        #pragma unroll
        for (int o = 1; o < 32; o <<= 1) {
            int u = __shfl_up_sync(0xffffffffu, i2, o);
            if (lane >= o) i2 += u;
        }
        wtot[lane] = i2 - s;    // exclusive warp offsets
    }
    __syncthreads();

    int basev = wtot[wid] + wexcl;
    #pragma unroll
    for (int i = 0; i < PERT; i++) {
        int idx = base_i + i;
        if (idx < NW) g_woff[idx] = basev + pre[i];
    }
}

// ============================================================
// K4: write means + reset accumulators. No smem, no syncthreads.
// seg = g_woff[v>>5] + popc(ballot-below); ballot recomputed from
// final counts (identical to K2's mask).
// ============================================================
__global__ void __launch_bounds__(1024)
k_out(float4* __restrict__ out4) {
    int v = blockIdx.x * 1024 + threadIdx.x;
    int cnt = (v < VTOTAL) ? __ldcg(&g_counts[v]) : 0;
    unsigned m = __ballot_sync(0xffffffffu, cnt > 0);

    if (cnt > 0) {
        int seg = __ldcg(&g_woff[v >> 5]) + __popc(m & ((1u << (v & 31)) - 1u));
        if (seg < MAX_VOX) {
            float4 s4 = __ldcg((const float4*)&g_sums[v]);
            float fc = (float)cnt;
            out4[seg] = make_float4(__fdiv_rn(s4.x, fc),
                                    __fdiv_rn(s4.y, fc),
                                    __fdiv_rn(s4.z, fc),
                                    __fdiv_rn(s4.w, fc));
        }
    }
    if (v < VTOTAL) {
        g_sums[v] = make_float4(0.f, 0.f, 0.f, 0.f);
        g_counts[v] = 0;
    }
}

// ============================================================
extern "C" void kernel_launch(void* const* d_in, const int* in_sizes, int n_in,
                              void* d_out, int out_size) {
    const float* clouds = (const float*)d_in[0];
    float4* out4 = (float4*)d_out;

    dim3 agrid((NPTS + 255) / 256, NBATCH);   // 782 x 4 blocks
    k_accum<<<agrid, 256>>>(clouds);

    int vblocks = (VTOTAL + 1023) / 1024;     // 210
    k_mask<<<vblocks, 1024>>>();
    k_scanw<<<1, 1024>>>();
    k_out<<<vblocks, 1024>>>(out4);
}